// round 1
// baseline (speedup 1.0000x reference)
#include <cuda_runtime.h>
#include <math.h>

// Shapes (fixed by the problem):
// B=2, S=8192 -> R = 16384 rows; H=2048; P=512; G=3P=1536; N=64 slots
#define R_ROWS   16384
#define H_DIM    2048
#define P_DIM    512
#define G_DIM    1536
#define N_SLOTS  64

// Output layout (concatenated, fp32):
// [0]                     surprise (1)
// [1 .. 2048]             prediction_error (2048)
// [2049 .. 4096]          predicted (2048)
// [4097 .. 135168]        mem_states_new (64*2048)
// [135169 .. 135232]      mem_strength_new (64)
// [135233 .. 135744]      new_pred_state (512)
#define OFF_SURPRISE 0
#define OFF_ERR      1
#define OFF_PRED     2049
#define OFF_MEM      4097
#define OFF_STR      135169
#define OFF_PSTATE   135233

// Device scratch (no cudaMalloc allowed)
__device__ float g_accum[H_DIM];      // raw column sums of hidden_states
__device__ float g_actual[H_DIM];     // accum / 16384
__device__ float g_predicted[H_DIM];
__device__ float g_xgru[H_DIM];
__device__ float g_gi[G_DIM];
__device__ float g_gh[G_DIM];
__device__ float g_surprise;

__device__ __forceinline__ float warp_reduce_sum(float v) {
#pragma unroll
    for (int o = 16; o > 0; o >>= 1) v += __shfl_xor_sync(0xFFFFFFFFu, v, o);
    return v;
}

__device__ __forceinline__ float sigmoidf_(float x) {
    return 1.0f / (1.0f + expf(-x));
}

// ---------------------------------------------------------------------------
// K_pred: predicted = pred_proj_w @ pred_state. Also zeros g_accum (blocks 0,1)
// — it runs before the big reduction in stream order, so the zeroing is done
// before any atomicAdd lands.
// grid 256 x 256 threads; one warp per output row (2048 rows).
// ---------------------------------------------------------------------------
__global__ void k_predicted(const float* __restrict__ W,   // (2048, 512)
                            const float* __restrict__ s,   // (512,)
                            float* __restrict__ out) {
    __shared__ float sh[P_DIM];

    if (blockIdx.x < 2) {
        // zero g_accum: 2 blocks * 256 threads * 1 float4 = 2048 floats
        float4 z = make_float4(0.f, 0.f, 0.f, 0.f);
        reinterpret_cast<float4*>(g_accum)[blockIdx.x * 256 + threadIdx.x] = z;
    }

    for (int i = threadIdx.x; i < P_DIM; i += 256) sh[i] = s[i];
    __syncthreads();

    int warp = threadIdx.x >> 5, lane = threadIdx.x & 31;
    int row = blockIdx.x * 8 + warp;          // 0..2047
    const float4* wr = reinterpret_cast<const float4*>(W + (size_t)row * P_DIM);
    float acc = 0.f;
#pragma unroll
    for (int j = lane; j < P_DIM / 4; j += 32) {
        float4 w = wr[j];
        acc += w.x * sh[4*j] + w.y * sh[4*j+1] + w.z * sh[4*j+2] + w.w * sh[4*j+3];
    }
    acc = warp_reduce_sum(acc);
    if (lane == 0) {
        g_predicted[row] = acc;
        out[OFF_PRED + row] = acc;
    }
}

// ---------------------------------------------------------------------------
// K_reduce: column sums of hidden_states (16384 x 2048) -> g_accum (atomics).
// grid (2, 256) x 256 threads; thread owns one float4 column, 64 rows/block.
// ---------------------------------------------------------------------------
__global__ void k_reduce(const float* __restrict__ hs) {
    const float4* p = reinterpret_cast<const float4*>(hs);
    int c4 = blockIdx.x * 256 + threadIdx.x;          // 0..511 float4 column
    int base = (blockIdx.y * 64) * (H_DIM / 4) + c4;  // row-major float4 index
    float4 acc = make_float4(0.f, 0.f, 0.f, 0.f);
#pragma unroll 8
    for (int r = 0; r < 64; r++) {
        float4 v = p[base + r * (H_DIM / 4)];
        acc.x += v.x; acc.y += v.y; acc.z += v.z; acc.w += v.w;
    }
    atomicAdd(&g_accum[c4 * 4 + 0], acc.x);
    atomicAdd(&g_accum[c4 * 4 + 1], acc.y);
    atomicAdd(&g_accum[c4 * 4 + 2], acc.z);
    atomicAdd(&g_accum[c4 * 4 + 3], acc.w);
}

// ---------------------------------------------------------------------------
// K_finalize: actual, prediction_error, surprise, mem_strength_new.
// single block, 1024 threads.
// ---------------------------------------------------------------------------
__global__ void k_finalize(const float* __restrict__ strength, // (64,)
                           const int* __restrict__ wptr,
                           const float* __restrict__ scale,
                           float* __restrict__ out) {
    __shared__ float red[32];
    __shared__ float s_surprise;

    float local = 0.f;
    for (int h = threadIdx.x; h < H_DIM; h += 1024) {
        float a = g_accum[h] * (1.0f / (float)R_ROWS);
        g_actual[h] = a;
        float e = a - g_predicted[h];
        out[OFF_ERR + h] = e;
        local += e * e;
    }
    local = warp_reduce_sum(local);
    int warp = threadIdx.x >> 5, lane = threadIdx.x & 31;
    if (lane == 0) red[warp] = local;
    __syncthreads();
    if (warp == 0) {
        float v = (lane < 32) ? red[lane] : 0.f;
        v = warp_reduce_sum(v);
        if (lane == 0) {
            float norm = sqrtf(v) * rsqrtf((float)H_DIM);
            float sp = sigmoidf_(scale[0] * norm);
            out[OFF_SURPRISE] = sp;
            g_surprise = sp;
            s_surprise = sp;
        }
    }
    __syncthreads();

    if (threadIdx.x < N_SLOTS) {
        // decay^8192 computed in double for accuracy
        float dec = (float)exp(8192.0 * log(0.999));
        int slot = wptr[0] % N_SLOTS;
        float v = (threadIdx.x == slot) ? s_surprise : strength[threadIdx.x] * dec;
        out[OFF_STR + threadIdx.x] = v;
    }
}

// ---------------------------------------------------------------------------
// K_xgru_mem: blocks [0,256): x_gru = input_proj_w @ actual (warp per row).
//             blocks [256,288): mem_states_new copy + slot write.
// ---------------------------------------------------------------------------
__global__ void k_xgru_mem(const float* __restrict__ ipw,  // (2048, 2048)
                           const float* __restrict__ mem,  // (64, 2048)
                           const int* __restrict__ wptr,
                           float* __restrict__ out) {
    if (blockIdx.x < 256) {
        __shared__ float sh[H_DIM];
        for (int i = threadIdx.x; i < H_DIM; i += 256) sh[i] = g_actual[i];
        __syncthreads();
        int warp = threadIdx.x >> 5, lane = threadIdx.x & 31;
        int row = blockIdx.x * 8 + warp;  // 0..2047
        const float4* wr = reinterpret_cast<const float4*>(ipw + (size_t)row * H_DIM);
        float acc = 0.f;
#pragma unroll 4
        for (int j = lane; j < H_DIM / 4; j += 32) {
            float4 w = wr[j];
            acc += w.x * sh[4*j] + w.y * sh[4*j+1] + w.z * sh[4*j+2] + w.w * sh[4*j+3];
        }
        acc = warp_reduce_sum(acc);
        if (lane == 0) g_xgru[row] = acc;
    } else {
        int slot = wptr[0] % N_SLOTS;
        float sp = g_surprise;
        int t = (blockIdx.x - 256) * 256 + threadIdx.x;   // 0..8191
        for (int j = t; j < N_SLOTS * H_DIM; j += 8192) {
            int row = j >> 11;          // /2048
            int col = j & (H_DIM - 1);
            float v = mem[j];
            if (row == slot) v = g_actual[col] * sp;
            out[OFF_MEM + j] = v;
        }
    }
}

// ---------------------------------------------------------------------------
// K_gates: blocks [0,192): gi = W_ih @ x_gru + b_ih  (1536 rows, K=2048)
//          blocks [192,384): gh = W_hh @ pred_state + b_hh (1536 rows, K=512)
// ---------------------------------------------------------------------------
__global__ void k_gates(const float* __restrict__ Wih,  // (1536, 2048)
                        const float* __restrict__ Whh,  // (1536, 512)
                        const float* __restrict__ bih,
                        const float* __restrict__ bhh,
                        const float* __restrict__ pstate) {
    __shared__ float sh[H_DIM];
    int warp = threadIdx.x >> 5, lane = threadIdx.x & 31;

    if (blockIdx.x < 192) {
        for (int i = threadIdx.x; i < H_DIM; i += 256) sh[i] = g_xgru[i];
        __syncthreads();
        int row = blockIdx.x * 8 + warp;  // 0..1535
        const float4* wr = reinterpret_cast<const float4*>(Wih + (size_t)row * H_DIM);
        float acc = 0.f;
#pragma unroll 4
        for (int j = lane; j < H_DIM / 4; j += 32) {
            float4 w = wr[j];
            acc += w.x * sh[4*j] + w.y * sh[4*j+1] + w.z * sh[4*j+2] + w.w * sh[4*j+3];
        }
        acc = warp_reduce_sum(acc);
        if (lane == 0) g_gi[row] = acc + bih[row];
    } else {
        for (int i = threadIdx.x; i < P_DIM; i += 256) sh[i] = pstate[i];
        __syncthreads();
        int row = (blockIdx.x - 192) * 8 + warp;  // 0..1535
        const float4* wr = reinterpret_cast<const float4*>(Whh + (size_t)row * P_DIM);
        float acc = 0.f;
#pragma unroll
        for (int j = lane; j < P_DIM / 4; j += 32) {
            float4 w = wr[j];
            acc += w.x * sh[4*j] + w.y * sh[4*j+1] + w.z * sh[4*j+2] + w.w * sh[4*j+3];
        }
        acc = warp_reduce_sum(acc);
        if (lane == 0) g_gh[row] = acc + bhh[row];
    }
}

// ---------------------------------------------------------------------------
// K_gru: final GRU cell combine. one block, 512 threads.
// ---------------------------------------------------------------------------
__global__ void k_gru(const float* __restrict__ pstate, float* __restrict__ out) {
    int p = threadIdx.x;  // 0..511
    float r = sigmoidf_(g_gi[p]           + g_gh[p]);
    float z = sigmoidf_(g_gi[P_DIM + p]   + g_gh[P_DIM + p]);
    float n = tanhf(g_gi[2*P_DIM + p] + r * g_gh[2*P_DIM + p]);
    out[OFF_PSTATE + p] = (1.0f - z) * n + z * pstate[p];
}

extern "C" void kernel_launch(void* const* d_in, const int* in_sizes, int n_in,
                              void* d_out, int out_size) {
    const float* hidden     = (const float*)d_in[0];
    const float* pred_state = (const float*)d_in[1];
    const float* mem_states = (const float*)d_in[2];
    const float* mem_str    = (const float*)d_in[3];
    const float* W_ih       = (const float*)d_in[4];
    const float* W_hh       = (const float*)d_in[5];
    const float* b_ih       = (const float*)d_in[6];
    const float* b_hh       = (const float*)d_in[7];
    const float* pp_w       = (const float*)d_in[8];
    const float* ip_w       = (const float*)d_in[9];
    const float* s_scale    = (const float*)d_in[10];
    const int*   write_ptr  = (const int*)d_in[11];
    float* out = (float*)d_out;

    // zeroing of g_accum is folded into k_predicted (runs before k_reduce)
    k_predicted<<<256, 256>>>(pp_w, pred_state, out);
    k_reduce<<<dim3(2, 256), 256>>>(hidden);
    k_finalize<<<1, 1024>>>(mem_str, write_ptr, s_scale, out);
    k_xgru_mem<<<288, 256>>>(ip_w, mem_states, write_ptr, out);
    k_gates<<<384, 256>>>(W_ih, W_hh, b_ih, b_hh, pred_state);
    k_gru<<<1, 512>>>(pred_state, out);
}